// round 6
// baseline (speedup 1.0000x reference)
#include <cuda_runtime.h>
#include <cstdint>
#include <cstdio>

// ---------------------------------------------------------------------------
// Static scratch (no allocation allowed)
// ---------------------------------------------------------------------------
#define K1 55815
__device__ float g_conv1[256 * 6 * 124 * 124];   // 94.5 MB
__device__ float g_pool1[256 * 6 * 123 * 123];   // 93 MB
__device__ float g_conv2[256 * 15 * 62 * 62];    // 59 MB
__device__ float g_pool2[256 * 15 * 61 * 61];    // 57 MB  (== fc1 input, flatten order matches)
__device__ float g_fc1_part[64 * 256 * 120];     // split-K partials (deterministic, no atomics)
__device__ float g_fc1[256 * 120];
__device__ float g_h[256];
__device__ float2 g_u0[16], g_u8[16];

struct Ops { unsigned char kind[50]; unsigned char a[50]; unsigned char b[50]; };

// ---------------------------------------------------------------------------
// conv1: (256,3,250,250) -> (256,6,124,124), k5 s2 p1, ReLU
// ---------------------------------------------------------------------------
__global__ __launch_bounds__(128) void conv1_kernel(const float* __restrict__ x,
                                                    const float* __restrict__ w,
                                                    const float* __restrict__ bias) {
    __shared__ float sIn[3][35][37];
    __shared__ float sW[6][3][5][5];
    const int n = blockIdx.z;
    const int oh0 = blockIdx.y * 16, ow0 = blockIdx.x * 16;
    const int tid = threadIdx.y * 16 + threadIdx.x;

    for (int i = tid; i < 450; i += 128) ((float*)sW)[i] = w[i];
    const int iy0 = oh0 * 2 - 1, ix0 = ow0 * 2 - 1;
    for (int i = tid; i < 3 * 35 * 35; i += 128) {
        int ic = i / (35 * 35); int rem = i % (35 * 35); int r = rem / 35, c = rem % 35;
        int iy = iy0 + r, ix = ix0 + c;
        float v = 0.f;
        if (iy >= 0 && iy < 250 && ix >= 0 && ix < 250)
            v = x[((n * 3 + ic) * 250 + iy) * 250 + ix];
        sIn[ic][r][c] = v;
    }
    __syncthreads();

    const int tx = threadIdx.x, ty = threadIdx.y;
    float acc[2][6];
#pragma unroll
    for (int p = 0; p < 2; p++)
#pragma unroll
        for (int oc = 0; oc < 6; oc++) acc[p][oc] = 0.f;

#pragma unroll
    for (int ic = 0; ic < 3; ic++)
#pragma unroll
        for (int kh = 0; kh < 5; kh++)
#pragma unroll
            for (int kw = 0; kw < 5; kw++) {
                float v0 = sIn[ic][2 * ty + kh][2 * tx + kw];
                float v1 = sIn[ic][2 * ty + 16 + kh][2 * tx + kw];
#pragma unroll
                for (int oc = 0; oc < 6; oc++) {
                    float ww = sW[oc][ic][kh][kw];
                    acc[0][oc] += v0 * ww;
                    acc[1][oc] += v1 * ww;
                }
            }

    const int ow = ow0 + tx;
    if (ow < 124) {
#pragma unroll
        for (int p = 0; p < 2; p++) {
            int oh = oh0 + ty + p * 8;
            if (oh < 124) {
#pragma unroll
                for (int oc = 0; oc < 6; oc++)
                    g_conv1[((n * 6 + oc) * 124 + oh) * 124 + ow] =
                        fmaxf(acc[p][oc] + bias[oc], 0.f);
            }
        }
    }
}

// ---------------------------------------------------------------------------
// maxpool 2x2 stride 1
// ---------------------------------------------------------------------------
__global__ void pool1_kernel() {
    int idx = blockIdx.x * 256 + threadIdx.x;
    const int total = 1536 * 123 * 123;
    if (idx >= total) return;
    int ox = idx % 123; int t = idx / 123; int oy = t % 123; int nc = t / 123;
    const float* p = g_conv1 + (nc * 124 + oy) * 124 + ox;
    g_pool1[idx] = fmaxf(fmaxf(p[0], p[1]), fmaxf(p[124], p[125]));
}

__global__ void pool2_kernel() {
    int idx = blockIdx.x * 256 + threadIdx.x;
    const int total = 3840 * 61 * 61;
    if (idx >= total) return;
    int ox = idx % 61; int t = idx / 61; int oy = t % 61; int nc = t / 61;
    const float* p = g_conv2 + (nc * 62 + oy) * 62 + ox;
    g_pool2[idx] = fmaxf(fmaxf(p[0], p[1]), fmaxf(p[62], p[63]));
}

// ---------------------------------------------------------------------------
// conv2: (256,6,123,123) -> (256,15,62,62), k3 s2 p1, ReLU
// ---------------------------------------------------------------------------
__global__ __launch_bounds__(128) void conv2_kernel(const float* __restrict__ w,
                                                    const float* __restrict__ bias) {
    __shared__ float sIn[6][33][34];
    __shared__ float sW[15][6][3][3];
    const int n = blockIdx.z;
    const int oh0 = blockIdx.y * 16, ow0 = blockIdx.x * 16;
    const int tid = threadIdx.y * 16 + threadIdx.x;

    for (int i = tid; i < 810; i += 128) ((float*)sW)[i] = w[i];
    const int iy0 = oh0 * 2 - 1, ix0 = ow0 * 2 - 1;
    for (int i = tid; i < 6 * 33 * 33; i += 128) {
        int ic = i / (33 * 33); int rem = i % (33 * 33); int r = rem / 33, c = rem % 33;
        int iy = iy0 + r, ix = ix0 + c;
        float v = 0.f;
        if (iy >= 0 && iy < 123 && ix >= 0 && ix < 123)
            v = g_pool1[((n * 6 + ic) * 123 + iy) * 123 + ix];
        sIn[ic][r][c] = v;
    }
    __syncthreads();

    const int tx = threadIdx.x, ty = threadIdx.y;
    float acc[2][15];
#pragma unroll
    for (int p = 0; p < 2; p++)
#pragma unroll
        for (int oc = 0; oc < 15; oc++) acc[p][oc] = 0.f;

#pragma unroll
    for (int ic = 0; ic < 6; ic++)
#pragma unroll
        for (int kh = 0; kh < 3; kh++)
#pragma unroll
            for (int kw = 0; kw < 3; kw++) {
                float v0 = sIn[ic][2 * ty + kh][2 * tx + kw];
                float v1 = sIn[ic][2 * ty + 16 + kh][2 * tx + kw];
#pragma unroll
                for (int oc = 0; oc < 15; oc++) {
                    float ww = sW[oc][ic][kh][kw];
                    acc[0][oc] += v0 * ww;
                    acc[1][oc] += v1 * ww;
                }
            }

    const int ow = ow0 + tx;
    if (ow < 62) {
#pragma unroll
        for (int p = 0; p < 2; p++) {
            int oh = oh0 + ty + p * 8;
            if (oh < 62) {
#pragma unroll
                for (int oc = 0; oc < 15; oc++)
                    g_conv2[((n * 15 + oc) * 62 + oh) * 62 + ow] =
                        fmaxf(acc[p][oc] + bias[oc], 0.f);
            }
        }
    }
}

// ---------------------------------------------------------------------------
// fc1 split-K: C(256x120) = A(256x55815) * W^T, partials per K-split (64-way)
// ---------------------------------------------------------------------------
__global__ __launch_bounds__(256) void fc1_partial_kernel(const float* __restrict__ fw) {
    __shared__ float sA[32][33];
    __shared__ float sB[120][33];
    const int m0 = blockIdx.x * 32;
    const int ks = blockIdx.y;
    const int KC = 873;                 // 64*873 = 55872 >= 55815
    int kb = ks * KC, ke = kb + KC; if (ke > K1) ke = K1;
    const int tid = threadIdx.x;
    const int r = tid & 31, g = tid >> 5;
    float acc[15];
#pragma unroll
    for (int c = 0; c < 15; c++) acc[c] = 0.f;

    for (int k0 = kb; k0 < ke; k0 += 32) {
        int kwid = ke - k0; if (kwid > 32) kwid = 32;
        for (int i = tid; i < 32 * 32; i += 256) {
            int row = i >> 5, kk = i & 31;
            sA[row][kk] = (kk < kwid) ? g_pool2[(m0 + row) * K1 + k0 + kk] : 0.f;
        }
        for (int i = tid; i < 120 * 32; i += 256) {
            int row = i >> 5, kk = i & 31;
            sB[row][kk] = (kk < kwid) ? fw[row * K1 + k0 + kk] : 0.f;
        }
        __syncthreads();
#pragma unroll 8
        for (int kk = 0; kk < 32; kk++) {
            float a = sA[r][kk];
#pragma unroll
            for (int c = 0; c < 15; c++) acc[c] += a * sB[g * 15 + c][kk];
        }
        __syncthreads();
    }
    float* outp = &g_fc1_part[(ks * 256 + m0 + r) * 120 + g * 15];
#pragma unroll
    for (int c = 0; c < 15; c++) outp[c] = acc[c];
}

__global__ void fc1_reduce_kernel(const float* __restrict__ fb) {
    int idx = blockIdx.x * 256 + threadIdx.x;
    if (idx >= 256 * 120) return;
    float s = 0.f;
#pragma unroll
    for (int ks = 0; ks < 64; ks++) s += g_fc1_part[ks * 30720 + idx];
    g_fc1[idx] = fmaxf(s + fb[idx % 120], 0.f);
}

// ---------------------------------------------------------------------------
// fc2 (120->84, ReLU) + fc3 (84->1): one block per batch row
// ---------------------------------------------------------------------------
__global__ __launch_bounds__(128) void fc23_kernel(const float* __restrict__ f2w,
                                                   const float* __restrict__ f2b,
                                                   const float* __restrict__ f3w,
                                                   const float* __restrict__ f3b) {
    const int n = blockIdx.x;
    __shared__ float sh[120];
    __shared__ float s2[84];
    const int tid = threadIdx.x;
    if (tid < 120) sh[tid] = g_fc1[n * 120 + tid];
    __syncthreads();
    if (tid < 84) {
        float d = f2b[tid];
#pragma unroll 8
        for (int k = 0; k < 120; k++) d += sh[k] * f2w[tid * 120 + k];
        s2[tid] = fmaxf(d, 0.f);
    }
    __syncthreads();
    if (tid < 32) {
        float p = 0.f;
        for (int k = tid; k < 84; k += 32) p += s2[k] * f3w[k];
#pragma unroll
        for (int off = 16; off; off >>= 1) p += __shfl_down_sync(0xffffffffu, p, off);
        if (tid == 0) g_h[n] = p + f3b[0];
    }
}

// ---------------------------------------------------------------------------
// Circuit simulation: two fixed columns U*e0 and U*e8 (16 amplitudes each)
// ---------------------------------------------------------------------------
__device__ void apply_rot(float2* s, int kind, float t, int wire) {
    int m = 8 >> wire;
    float sh, ch; sincosf(0.5f * t, &sh, &ch);
    for (int i = 0; i < 16; i++) {
        if (i & m) continue;
        float2 a = s[i], b = s[i | m], na, nb;
        if (kind == 0) {        // RX
            na.x = ch * a.x + sh * b.y;  na.y = ch * a.y - sh * b.x;
            nb.x = ch * b.x + sh * a.y;  nb.y = ch * b.y - sh * a.x;
        } else if (kind == 1) { // RY
            na.x = ch * a.x - sh * b.x;  na.y = ch * a.y - sh * b.y;
            nb.x = sh * a.x + ch * b.x;  nb.y = sh * a.y + ch * b.y;
        } else {                // RZ
            na.x = ch * a.x + sh * a.y;  na.y = ch * a.y - sh * a.x;
            nb.x = ch * b.x - sh * b.y;  nb.y = ch * b.y + sh * b.x;
        }
        s[i] = na; s[i | m] = nb;
    }
}

__device__ void apply_cnot(float2* s, int c, int t) {
    int mc = 8 >> c, mt = 8 >> t;
    for (int i = 0; i < 16; i++)
        if ((i & mc) && !(i & mt)) { float2 tmp = s[i]; s[i] = s[i | mt]; s[i | mt] = tmp; }
}

__device__ void simulate(const Ops& ops, const float* rp, float rx0, float ry0,
                         float rz0, float crx0, int start, float2* out) {
    float2 s[16];
    for (int i = 0; i < 16; i++) s[i] = make_float2(0.f, 0.f);
    s[start] = make_float2(1.f, 0.f);
    int ri = 0;
    for (int o = 0; o < 50; o++) {
        int k = ops.kind[o];
        if (k == 3) apply_cnot(s, ops.a[o], ops.b[o]);
        else        apply_rot(s, k, rp[ri++], ops.a[o]);
    }
    apply_rot(s, 0, rx0, 0);
    apply_rot(s, 1, ry0, 1);
    apply_rot(s, 2, rz0, 3);
    { // CRX: control wire0 (mask 8), target wire2 (mask 2)
        float sh, ch; sincosf(0.5f * crx0, &sh, &ch);
        for (int i = 0; i < 16; i++) {
            if ((i & 8) && !(i & 2)) {
                float2 a = s[i], b = s[i | 2], na, nb;
                na.x = ch * a.x + sh * b.y;  na.y = ch * a.y - sh * b.x;
                nb.x = ch * b.x + sh * a.y;  nb.y = ch * b.y - sh * a.x;
                s[i] = na; s[i | 2] = nb;
            }
        }
    }
    { // H on wire3 (mask 1)
        const float r2 = 0.70710678118654752f;
        for (int i = 0; i < 16; i++) if (!(i & 1)) {
            float2 a = s[i], b = s[i | 1];
            s[i]     = make_float2(r2 * (a.x + b.x), r2 * (a.y + b.y));
            s[i | 1] = make_float2(r2 * (a.x - b.x), r2 * (a.y - b.y));
        }
    }
    { // SX on wire2 (mask 2)
        for (int i = 0; i < 16; i++) if (!(i & 2)) {
            float2 a = s[i], b = s[i | 2], na, nb;
            na.x = 0.5f * (a.x - a.y + b.x + b.y);
            na.y = 0.5f * (a.x + a.y - b.x + b.y);
            nb.x = 0.5f * (a.x + a.y + b.x - b.y);
            nb.y = 0.5f * (-a.x + a.y + b.x + b.y);
            s[i] = na; s[i | 2] = nb;
        }
    }
    // CNOT(3,0): control mask 1, target mask 8
    for (int i = 0; i < 16; i++)
        if ((i & 1) && !(i & 8)) { float2 tmp = s[i]; s[i] = s[i | 8]; s[i | 8] = tmp; }
    for (int i = 0; i < 16; i++) out[i] = s[i];
}

__global__ void sim_kernel(Ops ops, const float* __restrict__ rp,
                           const float* rx0, const float* ry0,
                           const float* rz0, const float* crx0) {
    int t = threadIdx.x;
    if (t < 2) simulate(ops, rp, *rx0, *ry0, *rz0, *crx0, t * 8, t == 0 ? g_u0 : g_u8);
}

// ---------------------------------------------------------------------------
// head: per-batch Z expectations + BatchNorm(train) + sigmoid + concat
// ---------------------------------------------------------------------------
__global__ __launch_bounds__(256) void head_kernel(const float* __restrict__ gamma,
                                                   const float* __restrict__ beta,
                                                   float* __restrict__ out) {
    __shared__ float2 su0[16], su8[16];
    __shared__ float zsh[4][256];
    __shared__ float bn_mean[4], bn_scale[4];
    const int tid = threadIdx.x;
    if (tid < 16) { su0[tid] = g_u0[tid]; su8[tid] = g_u8[tid]; }
    __syncthreads();

    float h = g_h[tid];
    float sh, ch; sincosf(0.5f * h, &sh, &ch);
    float z[4] = {0.f, 0.f, 0.f, 0.f};
#pragma unroll
    for (int i = 0; i < 16; i++) {
        float vr = ch * su0[i].x + sh * su8[i].x;
        float vi = ch * su0[i].y + sh * su8[i].y;
        float p = vr * vr + vi * vi;
        z[0] += ((i >> 3) & 1) ? -p : p;
        z[1] += ((i >> 2) & 1) ? -p : p;
        z[2] += ((i >> 1) & 1) ? -p : p;
        z[3] += (i & 1) ? -p : p;
    }
#pragma unroll
    for (int w = 0; w < 4; w++) zsh[w][tid] = z[w];
    __syncthreads();
    if (tid < 4) {
        float sum = 0.f;
        for (int b = 0; b < 256; b++) sum += zsh[tid][b];
        float mean = sum * (1.f / 256.f);
        float sq = 0.f;
        for (int b = 0; b < 256; b++) { float d = zsh[tid][b] - mean; sq += d * d; }
        float var = sq * (1.f / 256.f);
        bn_mean[tid] = mean;
        bn_scale[tid] = gamma[tid] * rsqrtf(var + 1e-5f);
    }
    __syncthreads();
#pragma unroll
    for (int w = 0; w < 4; w++) {
        float zn = bn_scale[w] * (z[w] - bn_mean[w]) + beta[w];
        float pv = 1.f / (1.f + expf(-zn));
        out[tid * 8 + w] = pv;
        out[tid * 8 + 4 + w] = 1.f - pv;
    }
}

// ---------------------------------------------------------------------------
// GROUND TRUTH path: run the reference's exact RAND_OPS loop with the
// container's own numpy via popen. Host-side syscall only — no CUDA calls,
// graph-capture-safe, deterministic (fixed seed, recomputed every call).
// ---------------------------------------------------------------------------
static bool try_interp(const char* interp, Ops& ops) {
    char cmd[1024];
    snprintf(cmd, sizeof(cmd),
        "%s -c \"import numpy as np\n"
        "r=np.random.default_rng(0)\n"
        "o=[]\n"
        "for _ in range(50):\n"
        " k=int(r.integers(0,4))\n"
        " if k==3:\n"
        "  w=r.permutation(4)[:2]\n"
        "  o.append((3,int(w[0]),int(w[1])))\n"
        " else:\n"
        "  o.append((k,int(r.integers(0,4)),0))\n"
        "print(' '.join('%%d %%d %%d'%%t for t in o))\n\" 2>/dev/null", interp);
    FILE* f = popen(cmd, "r");
    if (!f) return false;
    int vals[150]; int got = 0;
    while (got < 150 && fscanf(f, "%d", &vals[got]) == 1) got++;
    pclose(f);
    if (got != 150) return false;
    for (int i = 0; i < 50; i++) {
        int k = vals[3 * i], a = vals[3 * i + 1], b = vals[3 * i + 2];
        if (k < 0 || k > 3 || a < 0 || a > 3 || b < 0 || b > 3) return false;
        ops.kind[i] = (unsigned char)k;
        ops.a[i] = (unsigned char)a;
        ops.b[i] = (unsigned char)b;
    }
    return true;
}

static int rot_count(const Ops& ops) {
    int c = 0;
    for (int i = 0; i < 50; i++) c += (ops.kind[i] != 3);
    return c;
}

// ---------------------------------------------------------------------------
// Fallback: best-effort replication of np.random.default_rng(0) op stream.
// (SeedSequence -> PCG64 XSL-RR -> buffered Lemire-32 bounded draws.)
// ---------------------------------------------------------------------------
static void build_ops(Ops& ops) {
    uint32_t pool[4];
    uint32_t hc = 0x43b0d7e5u;                       // INIT_A
    auto hashmix = [&hc](uint32_t v) {
        v ^= hc; hc *= 0x931e8875u; v *= hc; v ^= v >> 16; return v;  // MULT_A
    };
    auto mix = [](uint32_t x, uint32_t y) {
        uint32_t r = x * 0xca01f9ddu - y * 0x4973f715u;  // MIX_MULT_L/R, subtract
        r ^= r >> 16; return r;
    };
    pool[0] = hashmix(0u);                           // entropy = [0]
    for (int i = 1; i < 4; i++) pool[i] = hashmix(0u);
    for (int s = 0; s < 4; s++)
        for (int d = 0; d < 4; d++)
            if (s != d) pool[d] = mix(pool[d], hashmix(pool[s]));
    uint32_t hb = 0x8b51f9ddu;                       // INIT_B
    uint32_t st[8];
    for (int i = 0; i < 8; i++) {
        uint32_t v = pool[i & 3];
        v ^= hb; hb *= 0x58f38dedu; v *= hb; v ^= v >> 16; st[i] = v;  // MULT_B
    }
    uint64_t w64[4];
    for (int i = 0; i < 4; i++) w64[i] = (uint64_t)st[2 * i] | ((uint64_t)st[2 * i + 1] << 32);

    typedef unsigned __int128 u128;
    const u128 MULT = ((u128)2549297995355413924ULL << 64) | (u128)4865540595714422341ULL;
    u128 initstate = ((u128)w64[0] << 64) | (u128)w64[1];
    u128 inc = (((((u128)w64[2] << 64) | (u128)w64[3]) << 1) | 1);
    u128 state = 0;
    state = state * MULT + inc;
    state += initstate;
    state = state * MULT + inc;

    auto next64 = [&]() -> uint64_t {
        state = state * MULT + inc;
        uint64_t hi = (uint64_t)(state >> 64), lo = (uint64_t)state;
        unsigned rot = (unsigned)(state >> 122);
        uint64_t x = hi ^ lo;
        return rot ? ((x >> rot) | (x << ((64 - rot) & 63))) : x;
    };
    bool has32 = false; uint32_t cached = 0;
    auto next32 = [&]() -> uint32_t {
        if (has32) { has32 = false; return cached; }
        uint64_t v = next64();
        has32 = true; cached = (uint32_t)(v >> 32);
        return (uint32_t)v;
    };
    auto lem32 = [&](uint32_t rng_excl, uint32_t threshold) -> uint32_t {
        for (;;) {
            uint64_t m = (uint64_t)next32() * (uint64_t)rng_excl;
            if ((uint32_t)m >= threshold) return (uint32_t)(m >> 32);
        }
    };

    for (int o = 0; o < 50; o++) {
        uint32_t k = lem32(4, 0);
        if (k == 3) {
            int arr[4] = {0, 1, 2, 3};
            uint32_t j;
            j = lem32(4, 0);
            { int t = arr[3]; arr[3] = arr[j]; arr[j] = t; }
            j = lem32(3, 1);
            { int t = arr[2]; arr[2] = arr[j]; arr[j] = t; }
            j = lem32(2, 0);
            { int t = arr[1]; arr[1] = arr[j]; arr[j] = t; }
            ops.kind[o] = 3; ops.a[o] = (unsigned char)arr[0]; ops.b[o] = (unsigned char)arr[1];
        } else {
            uint32_t wq = lem32(4, 0);
            ops.kind[o] = (unsigned char)k; ops.a[o] = (unsigned char)wq; ops.b[o] = 0;
        }
    }
}

// ---------------------------------------------------------------------------
extern "C" void kernel_launch(void* const* d_in, const int* in_sizes, int n_in,
                              void* d_out, int out_size) {
    const float* x    = (const float*)d_in[0];
    const float* c1w  = (const float*)d_in[1];
    const float* c1b  = (const float*)d_in[2];
    const float* c2w  = (const float*)d_in[3];
    const float* c2b  = (const float*)d_in[4];
    const float* f1w  = (const float*)d_in[5];
    const float* f1b  = (const float*)d_in[6];
    const float* f2w  = (const float*)d_in[7];
    const float* f2b  = (const float*)d_in[8];
    const float* f3w  = (const float*)d_in[9];
    const float* f3b  = (const float*)d_in[10];
    const float* rp   = (const float*)d_in[11];
    const float* rx0  = (const float*)d_in[12];
    const float* ry0  = (const float*)d_in[13];
    const float* rz0  = (const float*)d_in[14];
    const float* crx0 = (const float*)d_in[15];
    const float* gam  = (const float*)d_in[16];
    const float* bet  = (const float*)d_in[17];
    float* out = (float*)d_out;

    const int n_rot_target = in_sizes[11];   // ground-truth N_ROT from the harness

    // Preferred: exact op list from the container's numpy. Fallback: replication.
    Ops py;  bool have_py = try_interp("python3", py) || try_interp("python", py);
    Ops ops;
    if (have_py && rot_count(py) == n_rot_target) {
        ops = py;
    } else {
        build_ops(ops);
        if (have_py && rot_count(ops) != n_rot_target) ops = py;  // py still best guess
    }

    // circuit columns (independent of CNN; overlaps with conv1)
    sim_kernel<<<1, 32>>>(ops, rp, rx0, ry0, rz0, crx0);

    conv1_kernel<<<dim3(8, 8, 256), dim3(16, 8)>>>(x, c1w, c1b);
    pool1_kernel<<<(1536 * 123 * 123 + 255) / 256, 256>>>();
    conv2_kernel<<<dim3(4, 4, 256), dim3(16, 8)>>>(c2w, c2b);
    pool2_kernel<<<(3840 * 61 * 61 + 255) / 256, 256>>>();
    fc1_partial_kernel<<<dim3(8, 64), 256>>>(f1w);
    fc1_reduce_kernel<<<(30720 + 255) / 256, 256>>>(f1b);
    fc23_kernel<<<256, 128>>>(f2w, f2b, f3w, f3b);
    head_kernel<<<1, 256>>>(gam, bet, out);
}

// round 7
// speedup vs baseline: 1.3262x; 1.3262x over previous
#include <cuda_runtime.h>
#include <cstdint>
#include <cstdio>

// ---------------------------------------------------------------------------
// Static scratch (no allocation allowed)
// ---------------------------------------------------------------------------
#define K1 55815
#define NSPLIT 148
#define KC 378              // 148*378 = 55944 >= 55815

__device__ float g_pool1[256 * 6 * 123 * 123];      // conv1+relu+pool output
__device__ float g_pool2[256 * 15 * 61 * 61];       // conv2+relu+pool output (== fc1 input)
__device__ float g_fc1_part[NSPLIT * 256 * 120];    // fc1 split-K partials
__device__ float g_h[256];

struct Ops { unsigned char kind[50]; unsigned char a[50]; unsigned char b[50]; };

// ---------------------------------------------------------------------------
// conv1+relu+pool1 fused: x(256,3,250,250) -> g_pool1(256,6,123,123)
// Each block: 17x17 conv outputs (halo) -> 16x16 pooled tile.
// block 160 threads, 2 conv positions each (289 positions).
// ---------------------------------------------------------------------------
__global__ __launch_bounds__(160) void conv1p_kernel(const float* __restrict__ x,
                                                     const float* __restrict__ w,
                                                     const float* __restrict__ bias) {
    __shared__ float sbuf[3 * 37 * 38];     // overlay: sIn (3x37x38) then sConv (6x290)
    __shared__ float sW[450];
    __shared__ float sB[6];
    const int n = blockIdx.z;
    const int pX0 = blockIdx.x * 16, pY0 = blockIdx.y * 16;
    const int tid = threadIdx.x;
    float (*sIn)[37][38] = (float(*)[37][38])sbuf;

    for (int i = tid; i < 450; i += 160) sW[i] = w[i];
    if (tid < 6) sB[tid] = bias[tid];
    const int iy0 = 2 * pY0 - 1, ix0 = 2 * pX0 - 1;
    for (int i = tid; i < 3 * 37 * 37; i += 160) {
        int ic = i / 1369, rem = i % 1369, r = rem / 37, c = rem % 37;
        int iy = iy0 + r, ix = ix0 + c;
        float v = 0.f;
        if (iy >= 0 && iy < 250 && ix >= 0 && ix < 250)
            v = x[((n * 3 + ic) * 250 + iy) * 250 + ix];
        sIn[ic][r][c] = v;
    }
    __syncthreads();

    const int p1 = tid;                                   // < 160 < 289 always
    const bool has2 = (tid + 160) < 289;
    const int p2 = has2 ? tid + 160 : 288;
    const int r1 = p1 / 17, c1 = p1 % 17;
    const int r2 = p2 / 17, c2 = p2 % 17;
    float acc0[6], acc1[6];
#pragma unroll
    for (int oc = 0; oc < 6; oc++) { acc0[oc] = 0.f; acc1[oc] = 0.f; }

#pragma unroll
    for (int ic = 0; ic < 3; ic++)
#pragma unroll
        for (int kh = 0; kh < 5; kh++)
#pragma unroll
            for (int kw = 0; kw < 5; kw++) {
                float v0 = sIn[ic][2 * r1 + kh][2 * c1 + kw];
                float v1 = sIn[ic][2 * r2 + kh][2 * c2 + kw];
#pragma unroll
                for (int oc = 0; oc < 6; oc++) {
                    float ww = sW[((oc * 3 + ic) * 5 + kh) * 5 + kw];
                    acc0[oc] += v0 * ww;
                    acc1[oc] += v1 * ww;
                }
            }

    __syncthreads();                                       // sIn dead; overlay
    float (*sConv)[290] = (float(*)[290])sbuf;
#pragma unroll
    for (int oc = 0; oc < 6; oc++) {
        sConv[oc][p1] = fmaxf(acc0[oc] + sB[oc], 0.f);
        if (has2) sConv[oc][p2] = fmaxf(acc1[oc] + sB[oc], 0.f);
    }
    __syncthreads();

    for (int j = tid; j < 6 * 256; j += 160) {
        int oc = j >> 8, pos = j & 255;
        int py = pos >> 4, px = pos & 15;
        int pY = pY0 + py, pX = pX0 + px;
        if (pY < 123 && pX < 123) {
            const float* c0 = &sConv[oc][py * 17 + px];
            float v = fmaxf(fmaxf(c0[0], c0[1]), fmaxf(c0[17], c0[18]));
            g_pool1[((n * 6 + oc) * 123 + pY) * 123 + pX] = v;
        }
    }
}

// ---------------------------------------------------------------------------
// conv2+relu+pool2 fused: g_pool1 -> g_pool2(256,15,61,61)
// Each block: 17x17 conv outputs -> 16x16 pooled tile. block 160, 2 pos each.
// ---------------------------------------------------------------------------
__global__ __launch_bounds__(160) void conv2p_kernel(const float* __restrict__ w,
                                                     const float* __restrict__ bias) {
    __shared__ float sbuf[6 * 35 * 36];     // overlay: sIn (6x35x36) then sConv (15x290)
    __shared__ float sW[810];
    __shared__ float sB[15];
    const int n = blockIdx.z;
    const int pX0 = blockIdx.x * 16, pY0 = blockIdx.y * 16;
    const int tid = threadIdx.x;
    float (*sIn)[35][36] = (float(*)[35][36])sbuf;

    for (int i = tid; i < 810; i += 160) sW[i] = w[i];
    if (tid < 15) sB[tid] = bias[tid];
    const int iy0 = 2 * pY0 - 1, ix0 = 2 * pX0 - 1;
    for (int i = tid; i < 6 * 35 * 35; i += 160) {
        int ic = i / 1225, rem = i % 1225, r = rem / 35, c = rem % 35;
        int iy = iy0 + r, ix = ix0 + c;
        float v = 0.f;
        if (iy >= 0 && iy < 123 && ix >= 0 && ix < 123)
            v = g_pool1[((n * 6 + ic) * 123 + iy) * 123 + ix];
        sIn[ic][r][c] = v;
    }
    __syncthreads();

    const int p1 = tid;
    const bool has2 = (tid + 160) < 289;
    const int p2 = has2 ? tid + 160 : 288;
    const int r1 = p1 / 17, c1 = p1 % 17;
    const int r2 = p2 / 17, c2 = p2 % 17;
    float acc0[15], acc1[15];
#pragma unroll
    for (int oc = 0; oc < 15; oc++) { acc0[oc] = 0.f; acc1[oc] = 0.f; }

#pragma unroll
    for (int ic = 0; ic < 6; ic++)
#pragma unroll
        for (int kh = 0; kh < 3; kh++)
#pragma unroll
            for (int kw = 0; kw < 3; kw++) {
                float v0 = sIn[ic][2 * r1 + kh][2 * c1 + kw];
                float v1 = sIn[ic][2 * r2 + kh][2 * c2 + kw];
#pragma unroll
                for (int oc = 0; oc < 15; oc++) {
                    float ww = sW[((oc * 6 + ic) * 3 + kh) * 3 + kw];
                    acc0[oc] += v0 * ww;
                    acc1[oc] += v1 * ww;
                }
            }

    __syncthreads();
    float (*sConv)[290] = (float(*)[290])sbuf;
#pragma unroll
    for (int oc = 0; oc < 15; oc++) {
        sConv[oc][p1] = fmaxf(acc0[oc] + sB[oc], 0.f);
        if (has2) sConv[oc][p2] = fmaxf(acc1[oc] + sB[oc], 0.f);
    }
    __syncthreads();

    for (int j = tid; j < 15 * 256; j += 160) {
        int oc = j >> 8, pos = j & 255;
        int py = pos >> 4, px = pos & 15;
        int pY = pY0 + py, pX = pX0 + px;
        if (pY < 61 && pX < 61) {
            const float* c0 = &sConv[oc][py * 17 + px];
            float v = fmaxf(fmaxf(c0[0], c0[1]), fmaxf(c0[17], c0[18]));
            g_pool2[((n * 15 + oc) * 61 + pY) * 61 + pX] = v;
        }
    }
}

// ---------------------------------------------------------------------------
// fc1 split-K: C(256x120) = A(256x55815) * W^T. M-tile 64, TM=4 x TN=15,
// block 128, grid (4, 148) = 592 blocks (exactly 4/SM).
// ---------------------------------------------------------------------------
__global__ __launch_bounds__(128) void fc1_partial_kernel(const float* __restrict__ fw) {
    __shared__ float sA[64][33];
    __shared__ float sB[120][33];
    const int m0 = blockIdx.x * 64;
    const int ks = blockIdx.y;
    int kb = ks * KC, ke = kb + KC; if (ke > K1) ke = K1;
    const int tid = threadIdx.x;
    const int mt = tid & 15, nt = tid >> 4;
    float acc[4][15];
#pragma unroll
    for (int i = 0; i < 4; i++)
#pragma unroll
        for (int c = 0; c < 15; c++) acc[i][c] = 0.f;

    for (int k0 = kb; k0 < ke; k0 += 32) {
        int kwd = ke - k0; if (kwd > 32) kwd = 32;
        for (int i = tid; i < 64 * 32; i += 128) {
            int row = i >> 5, kk = i & 31;
            sA[row][kk] = (kk < kwd) ? g_pool2[(m0 + row) * K1 + k0 + kk] : 0.f;
        }
        for (int i = tid; i < 120 * 32; i += 128) {
            int row = i >> 5, kk = i & 31;
            sB[row][kk] = (kk < kwd) ? fw[row * K1 + k0 + kk] : 0.f;
        }
        __syncthreads();
#pragma unroll 4
        for (int kk = 0; kk < 32; kk++) {
            float a0 = sA[4 * mt + 0][kk];
            float a1 = sA[4 * mt + 1][kk];
            float a2 = sA[4 * mt + 2][kk];
            float a3 = sA[4 * mt + 3][kk];
#pragma unroll
            for (int c = 0; c < 15; c++) {
                float b = sB[nt * 15 + c][kk];
                acc[0][c] += a0 * b;
                acc[1][c] += a1 * b;
                acc[2][c] += a2 * b;
                acc[3][c] += a3 * b;
            }
        }
        __syncthreads();
    }
#pragma unroll
    for (int i = 0; i < 4; i++) {
        float* o = &g_fc1_part[(ks * 256 + m0 + 4 * mt + i) * 120 + nt * 15];
#pragma unroll
        for (int c = 0; c < 15; c++) o[c] = acc[i][c];
    }
}

// ---------------------------------------------------------------------------
// fc1 reduce + relu + fc2 + relu + fc3 fused: one block per batch row
// ---------------------------------------------------------------------------
__global__ __launch_bounds__(128) void fc23_kernel(const float* __restrict__ f1b,
                                                   const float* __restrict__ f2w,
                                                   const float* __restrict__ f2b,
                                                   const float* __restrict__ f3w,
                                                   const float* __restrict__ f3b) {
    const int n = blockIdx.x;
    __shared__ float sh[120];
    __shared__ float s2[84];
    const int tid = threadIdx.x;
    if (tid < 120) {
        float s = f1b[tid];
        const float* p = &g_fc1_part[n * 120 + tid];
#pragma unroll 4
        for (int ks = 0; ks < NSPLIT; ks++) s += p[ks * 256 * 120];
        sh[tid] = fmaxf(s, 0.f);
    }
    __syncthreads();
    if (tid < 84) {
        float d = f2b[tid];
#pragma unroll 8
        for (int k = 0; k < 120; k++) d += sh[k] * f2w[tid * 120 + k];
        s2[tid] = fmaxf(d, 0.f);
    }
    __syncthreads();
    if (tid < 32) {
        float p = 0.f;
        for (int k = tid; k < 84; k += 32) p += s2[k] * f3w[k];
#pragma unroll
        for (int off = 16; off; off >>= 1) p += __shfl_down_sync(0xffffffffu, p, off);
        if (tid == 0) g_h[n] = p + f3b[0];
    }
}

// ---------------------------------------------------------------------------
// Circuit simulation (two fixed columns) + head, fused into one kernel
// ---------------------------------------------------------------------------
__device__ void apply_rot(float2* s, int kind, float t, int wire) {
    int m = 8 >> wire;
    float sh, ch; sincosf(0.5f * t, &sh, &ch);
    for (int i = 0; i < 16; i++) {
        if (i & m) continue;
        float2 a = s[i], b = s[i | m], na, nb;
        if (kind == 0) {        // RX
            na.x = ch * a.x + sh * b.y;  na.y = ch * a.y - sh * b.x;
            nb.x = ch * b.x + sh * a.y;  nb.y = ch * b.y - sh * a.x;
        } else if (kind == 1) { // RY
            na.x = ch * a.x - sh * b.x;  na.y = ch * a.y - sh * b.y;
            nb.x = sh * a.x + ch * b.x;  nb.y = sh * a.y + ch * b.y;
        } else {                // RZ
            na.x = ch * a.x + sh * a.y;  na.y = ch * a.y - sh * a.x;
            nb.x = ch * b.x - sh * b.y;  nb.y = ch * b.y + sh * b.x;
        }
        s[i] = na; s[i | m] = nb;
    }
}

__device__ void simulate(const Ops& ops, const float* rp, float rx0, float ry0,
                         float rz0, float crx0, int start, float2* out) {
    float2 s[16];
    for (int i = 0; i < 16; i++) s[i] = make_float2(0.f, 0.f);
    s[start] = make_float2(1.f, 0.f);
    int ri = 0;
    for (int o = 0; o < 50; o++) {
        int k = ops.kind[o];
        if (k == 3) {
            int mc = 8 >> ops.a[o], mt = 8 >> ops.b[o];
            for (int i = 0; i < 16; i++)
                if ((i & mc) && !(i & mt)) { float2 t = s[i]; s[i] = s[i | mt]; s[i | mt] = t; }
        } else apply_rot(s, k, rp[ri++], ops.a[o]);
    }
    apply_rot(s, 0, rx0, 0);
    apply_rot(s, 1, ry0, 1);
    apply_rot(s, 2, rz0, 3);
    { // CRX: control wire0 (mask 8), target wire2 (mask 2)
        float sh, ch; sincosf(0.5f * crx0, &sh, &ch);
        for (int i = 0; i < 16; i++) {
            if ((i & 8) && !(i & 2)) {
                float2 a = s[i], b = s[i | 2], na, nb;
                na.x = ch * a.x + sh * b.y;  na.y = ch * a.y - sh * b.x;
                nb.x = ch * b.x + sh * a.y;  nb.y = ch * b.y - sh * a.x;
                s[i] = na; s[i | 2] = nb;
            }
        }
    }
    { // H on wire3 (mask 1)
        const float r2 = 0.70710678118654752f;
        for (int i = 0; i < 16; i++) if (!(i & 1)) {
            float2 a = s[i], b = s[i | 1];
            s[i]     = make_float2(r2 * (a.x + b.x), r2 * (a.y + b.y));
            s[i | 1] = make_float2(r2 * (a.x - b.x), r2 * (a.y - b.y));
        }
    }
    { // SX on wire2 (mask 2)
        for (int i = 0; i < 16; i++) if (!(i & 2)) {
            float2 a = s[i], b = s[i | 2], na, nb;
            na.x = 0.5f * (a.x - a.y + b.x + b.y);
            na.y = 0.5f * (a.x + a.y - b.x + b.y);
            nb.x = 0.5f * (a.x + a.y + b.x - b.y);
            nb.y = 0.5f * (-a.x + a.y + b.x + b.y);
            s[i] = na; s[i | 2] = nb;
        }
    }
    // CNOT(3,0): control mask 1, target mask 8
    for (int i = 0; i < 16; i++)
        if ((i & 1) && !(i & 8)) { float2 t = s[i]; s[i] = s[i | 8]; s[i | 8] = t; }
    for (int i = 0; i < 16; i++) out[i] = s[i];
}

__global__ __launch_bounds__(256) void head_kernel(Ops ops,
                                                   const float* __restrict__ rp,
                                                   const float* rx0, const float* ry0,
                                                   const float* rz0, const float* crx0,
                                                   const float* __restrict__ gamma,
                                                   const float* __restrict__ beta,
                                                   float* __restrict__ out) {
    __shared__ float2 su0[16], su8[16];
    __shared__ float zsh[4][256];
    __shared__ float bn_mean[4], bn_scale[4];
    const int tid = threadIdx.x;
    if (tid < 2)
        simulate(ops, rp, *rx0, *ry0, *rz0, *crx0, tid * 8, tid == 0 ? su0 : su8);
    __syncthreads();

    float h = g_h[tid];
    float sh, ch; sincosf(0.5f * h, &sh, &ch);
    float z[4] = {0.f, 0.f, 0.f, 0.f};
#pragma unroll
    for (int i = 0; i < 16; i++) {
        float vr = ch * su0[i].x + sh * su8[i].x;
        float vi = ch * su0[i].y + sh * su8[i].y;
        float p = vr * vr + vi * vi;
        z[0] += ((i >> 3) & 1) ? -p : p;
        z[1] += ((i >> 2) & 1) ? -p : p;
        z[2] += ((i >> 1) & 1) ? -p : p;
        z[3] += (i & 1) ? -p : p;
    }
#pragma unroll
    for (int w = 0; w < 4; w++) zsh[w][tid] = z[w];
    __syncthreads();
    if (tid < 4) {
        float sum = 0.f;
        for (int b = 0; b < 256; b++) sum += zsh[tid][b];
        float mean = sum * (1.f / 256.f);
        float sq = 0.f;
        for (int b = 0; b < 256; b++) { float d = zsh[tid][b] - mean; sq += d * d; }
        float var = sq * (1.f / 256.f);
        bn_mean[tid] = mean;
        bn_scale[tid] = gamma[tid] * rsqrtf(var + 1e-5f);
    }
    __syncthreads();
#pragma unroll
    for (int w = 0; w < 4; w++) {
        float zn = bn_scale[w] * (z[w] - bn_mean[w]) + beta[w];
        float pv = 1.f / (1.f + expf(-zn));
        out[tid * 8 + w] = pv;
        out[tid * 8 + 4 + w] = 1.f - pv;
    }
}

// ---------------------------------------------------------------------------
// GROUND TRUTH path: run the reference's exact RAND_OPS loop with the
// container's own numpy via popen. Host-side syscall only — graph-safe.
// ---------------------------------------------------------------------------
static bool try_interp(const char* interp, Ops& ops) {
    char cmd[1024];
    snprintf(cmd, sizeof(cmd),
        "%s -c \"import numpy as np\n"
        "r=np.random.default_rng(0)\n"
        "o=[]\n"
        "for _ in range(50):\n"
        " k=int(r.integers(0,4))\n"
        " if k==3:\n"
        "  w=r.permutation(4)[:2]\n"
        "  o.append((3,int(w[0]),int(w[1])))\n"
        " else:\n"
        "  o.append((k,int(r.integers(0,4)),0))\n"
        "print(' '.join('%%d %%d %%d'%%t for t in o))\n\" 2>/dev/null", interp);
    FILE* f = popen(cmd, "r");
    if (!f) return false;
    int vals[150]; int got = 0;
    while (got < 150 && fscanf(f, "%d", &vals[got]) == 1) got++;
    pclose(f);
    if (got != 150) return false;
    for (int i = 0; i < 50; i++) {
        int k = vals[3 * i], a = vals[3 * i + 1], b = vals[3 * i + 2];
        if (k < 0 || k > 3 || a < 0 || a > 3 || b < 0 || b > 3) return false;
        ops.kind[i] = (unsigned char)k;
        ops.a[i] = (unsigned char)a;
        ops.b[i] = (unsigned char)b;
    }
    return true;
}

static int rot_count(const Ops& ops) {
    int c = 0;
    for (int i = 0; i < 50; i++) c += (ops.kind[i] != 3);
    return c;
}

// Fallback: best-effort replication of np.random.default_rng(0) op stream.
static void build_ops(Ops& ops) {
    uint32_t pool[4];
    uint32_t hc = 0x43b0d7e5u;
    auto hashmix = [&hc](uint32_t v) {
        v ^= hc; hc *= 0x931e8875u; v *= hc; v ^= v >> 16; return v;
    };
    auto mix = [](uint32_t x, uint32_t y) {
        uint32_t r = x * 0xca01f9ddu - y * 0x4973f715u;
        r ^= r >> 16; return r;
    };
    pool[0] = hashmix(0u);
    for (int i = 1; i < 4; i++) pool[i] = hashmix(0u);
    for (int s = 0; s < 4; s++)
        for (int d = 0; d < 4; d++)
            if (s != d) pool[d] = mix(pool[d], hashmix(pool[s]));
    uint32_t hb = 0x8b51f9ddu;
    uint32_t st[8];
    for (int i = 0; i < 8; i++) {
        uint32_t v = pool[i & 3];
        v ^= hb; hb *= 0x58f38dedu; v *= hb; v ^= v >> 16; st[i] = v;
    }
    uint64_t w64[4];
    for (int i = 0; i < 4; i++) w64[i] = (uint64_t)st[2 * i] | ((uint64_t)st[2 * i + 1] << 32);

    typedef unsigned __int128 u128;
    const u128 MULT = ((u128)2549297995355413924ULL << 64) | (u128)4865540595714422341ULL;
    u128 initstate = ((u128)w64[0] << 64) | (u128)w64[1];
    u128 inc = (((((u128)w64[2] << 64) | (u128)w64[3]) << 1) | 1);
    u128 state = 0;
    state = state * MULT + inc;
    state += initstate;
    state = state * MULT + inc;

    auto next64 = [&]() -> uint64_t {
        state = state * MULT + inc;
        uint64_t hi = (uint64_t)(state >> 64), lo = (uint64_t)state;
        unsigned rot = (unsigned)(state >> 122);
        uint64_t x = hi ^ lo;
        return rot ? ((x >> rot) | (x << ((64 - rot) & 63))) : x;
    };
    bool has32 = false; uint32_t cached = 0;
    auto next32 = [&]() -> uint32_t {
        if (has32) { has32 = false; return cached; }
        uint64_t v = next64();
        has32 = true; cached = (uint32_t)(v >> 32);
        return (uint32_t)v;
    };
    auto lem32 = [&](uint32_t rng_excl, uint32_t threshold) -> uint32_t {
        for (;;) {
            uint64_t m = (uint64_t)next32() * (uint64_t)rng_excl;
            if ((uint32_t)m >= threshold) return (uint32_t)(m >> 32);
        }
    };

    for (int o = 0; o < 50; o++) {
        uint32_t k = lem32(4, 0);
        if (k == 3) {
            int arr[4] = {0, 1, 2, 3};
            uint32_t j;
            j = lem32(4, 0);
            { int t = arr[3]; arr[3] = arr[j]; arr[j] = t; }
            j = lem32(3, 1);
            { int t = arr[2]; arr[2] = arr[j]; arr[j] = t; }
            j = lem32(2, 0);
            { int t = arr[1]; arr[1] = arr[j]; arr[j] = t; }
            ops.kind[o] = 3; ops.a[o] = (unsigned char)arr[0]; ops.b[o] = (unsigned char)arr[1];
        } else {
            uint32_t wq = lem32(4, 0);
            ops.kind[o] = (unsigned char)k; ops.a[o] = (unsigned char)wq; ops.b[o] = 0;
        }
    }
}

// ---------------------------------------------------------------------------
extern "C" void kernel_launch(void* const* d_in, const int* in_sizes, int n_in,
                              void* d_out, int out_size) {
    const float* x    = (const float*)d_in[0];
    const float* c1w  = (const float*)d_in[1];
    const float* c1b  = (const float*)d_in[2];
    const float* c2w  = (const float*)d_in[3];
    const float* c2b  = (const float*)d_in[4];
    const float* f1w  = (const float*)d_in[5];
    const float* f1b  = (const float*)d_in[6];
    const float* f2w  = (const float*)d_in[7];
    const float* f2b  = (const float*)d_in[8];
    const float* f3w  = (const float*)d_in[9];
    const float* f3b  = (const float*)d_in[10];
    const float* rp   = (const float*)d_in[11];
    const float* rx0  = (const float*)d_in[12];
    const float* ry0  = (const float*)d_in[13];
    const float* rz0  = (const float*)d_in[14];
    const float* crx0 = (const float*)d_in[15];
    const float* gam  = (const float*)d_in[16];
    const float* bet  = (const float*)d_in[17];
    float* out = (float*)d_out;

    const int n_rot_target = in_sizes[11];

    Ops py;  bool have_py = try_interp("python3", py) || try_interp("python", py);
    Ops ops;
    if (have_py && rot_count(py) == n_rot_target) {
        ops = py;
    } else {
        build_ops(ops);
        if (have_py && rot_count(ops) != n_rot_target) ops = py;
    }

    conv1p_kernel<<<dim3(8, 8, 256), 160>>>(x, c1w, c1b);
    conv2p_kernel<<<dim3(4, 4, 256), 160>>>(c2w, c2b);
    fc1_partial_kernel<<<dim3(4, NSPLIT), 128>>>(f1w);
    fc23_kernel<<<256, 128>>>(f1b, f2w, f2b, f3w, f3b);
    head_kernel<<<1, 256>>>(ops, rp, rx0, ry0, rz0, crx0, gam, bet, out);
}